// round 2
// baseline (speedup 1.0000x reference)
#include <cuda_runtime.h>

#define SQ 512
#define DM 512
#define NH 8
#define DH 64

// ---------------- scratch (static device globals; no allocation) ----------------
__device__ __align__(16) float g_qu[NH*SQ*DH];   // (q proj)+u   [h][s][d]
__device__ __align__(16) float g_qv[NH*SQ*DH];   // (q proj)+v   [h][s][d]
__device__ __align__(16) float g_kh[NH*SQ*DH];   // k proj       [h][s][d]
__device__ __align__(16) float g_vh[NH*SQ*DH];   // v proj       [h][s][d]
__device__ __align__(16) float g_t [NH*SQ*SQ];   // t[h][q][D]
__device__ __align__(16) float g_ac[NH*SQ*SQ];   // A_C[h][q][k]
__device__ __align__(16) float g_at[NH*SQ*SQ];   // attn[h][q][k]
__device__ __align__(16) float g_o [NH*SQ*DH];   // out[h][q][d]

__device__ __forceinline__ void ffma2(unsigned long long& d,
                                      unsigned long long a,
                                      unsigned long long b) {
    asm("fma.rn.f32x2 %0, %1, %2, %0;" : "+l"(d) : "l"(a), "l"(b));
}

// ---------------- K1: q/k/v projections (fused via blockIdx.z) ----------------
// C = X @ W + b ; output scattered into [h][s][d] layout; mode 0 also adds u/v.
__global__ void __launch_bounds__(256) proj_kernel(
    const float* __restrict__ Xq, const float* __restrict__ Xk, const float* __restrict__ Xv,
    const float* __restrict__ Wq, const float* __restrict__ bq,
    const float* __restrict__ Wk, const float* __restrict__ bk,
    const float* __restrict__ Wv, const float* __restrict__ bv,
    const float* __restrict__ u,  const float* __restrict__ v)
{
    const int mode = blockIdx.z;
    const float* X    = (mode == 0) ? Xq : (mode == 1) ? Xk : Xv;
    const float* W    = (mode == 0) ? Wq : (mode == 1) ? Wk : Wv;
    const float* bias = (mode == 0) ? bq : (mode == 1) ? bk : bv;

    __shared__ __align__(16) float As[16][64];  // [k][m]
    __shared__ __align__(16) float Bs[16][64];  // [k][n]

    const int tid = threadIdx.x;
    const int m0 = blockIdx.y * 64, n0 = blockIdx.x * 64;
    const int ty = tid >> 4, tx = tid & 15;

    const int aRow = tid >> 2, aK = (tid & 3) * 4;
    const int bK = tid >> 4, bN = (tid & 15) * 4;

    float c[4][4] = {};

    for (int k0 = 0; k0 < DM; k0 += 16) {
        float4 av = *(const float4*)&X[(size_t)(m0 + aRow) * DM + k0 + aK];
        As[aK + 0][aRow] = av.x; As[aK + 1][aRow] = av.y;
        As[aK + 2][aRow] = av.z; As[aK + 3][aRow] = av.w;
        *(float4*)&Bs[bK][bN] = *(const float4*)&W[(size_t)(k0 + bK) * DM + n0 + bN];
        __syncthreads();
        #pragma unroll
        for (int kk = 0; kk < 16; kk++) {
            float4 a4 = *(float4*)&As[kk][ty * 4];
            float4 b4 = *(float4*)&Bs[kk][tx * 4];
            float aa[4] = {a4.x, a4.y, a4.z, a4.w};
            float bb[4] = {b4.x, b4.y, b4.z, b4.w};
            #pragma unroll
            for (int i = 0; i < 4; i++)
                #pragma unroll
                for (int j = 0; j < 4; j++)
                    c[i][j] += aa[i] * bb[j];
        }
        __syncthreads();
    }

    #pragma unroll
    for (int i = 0; i < 4; i++) {
        int s = m0 + ty * 4 + i;
        #pragma unroll
        for (int j = 0; j < 4; j++) {
            int n = n0 + tx * 4 + j;
            float val = c[i][j] + bias[n];
            int h = n >> 6, d = n & 63;
            size_t o = (size_t)h * SQ * DH + (size_t)s * DH + d;
            if (mode == 0) {
                g_qu[o] = val + u[n];   // u flattened [h*64+d] == [n]
                g_qv[o] = val + v[n];
            } else if (mode == 1) {
                g_kh[o] = val;
            } else {
                g_vh[o] = val;
            }
        }
    }
}

// ---------------- K2: fused NT GEMMs (K=64): A_C and t ----------------
// z<8 : h=z    : C[q][k] = sum_d qu[h][q][d]*k[h][k][d]      -> g_ac
// z>=8: h=z-8  : C[s][D] = sum_d qv[h][s][d]*Wr[D][h*64+d]   -> g_t
__global__ void __launch_bounds__(256) nt64_kernel(const float* __restrict__ Wr)
{
    const int z = blockIdx.z;
    const int h = z & 7;
    const int which = z >> 3;
    const int n0 = blockIdx.x * 64, m0 = blockIdx.y * 64;

    __shared__ __align__(16) float Am[64][68];  // [d][m]
    __shared__ __align__(16) float Bm[64][68];  // [d][n]

    const int tid = threadIdx.x;
    const float* A = (which ? g_qv : g_qu) + (size_t)h * SQ * DH;
    const int rr = tid >> 4, d4 = (tid & 15) * 4;

    #pragma unroll
    for (int r = 0; r < 4; r++) {
        int m = rr + r * 16;
        float4 av = *(const float4*)&A[(size_t)(m0 + m) * DH + d4];
        Am[d4 + 0][m] = av.x; Am[d4 + 1][m] = av.y;
        Am[d4 + 2][m] = av.z; Am[d4 + 3][m] = av.w;
        float4 bv;
        if (which == 0)
            bv = *(const float4*)&g_kh[(size_t)h * SQ * DH + (size_t)(n0 + m) * DH + d4];
        else
            bv = *(const float4*)&Wr[(size_t)(n0 + m) * DM + h * DH + d4];
        Bm[d4 + 0][m] = bv.x; Bm[d4 + 1][m] = bv.y;
        Bm[d4 + 2][m] = bv.z; Bm[d4 + 3][m] = bv.w;
    }
    __syncthreads();

    const int ty = tid >> 4, tx = tid & 15;
    float c[4][4] = {};
    #pragma unroll 8
    for (int dd = 0; dd < 64; dd++) {
        float4 a4 = *(float4*)&Am[dd][ty * 4];
        float4 b4 = *(float4*)&Bm[dd][tx * 4];
        float aa[4] = {a4.x, a4.y, a4.z, a4.w};
        float bb[4] = {b4.x, b4.y, b4.z, b4.w};
        #pragma unroll
        for (int i = 0; i < 4; i++)
            #pragma unroll
            for (int j = 0; j < 4; j++)
                c[i][j] += aa[i] * bb[j];
    }

    float* Out = which ? g_t : g_ac;
    #pragma unroll
    for (int i = 0; i < 4; i++)
        #pragma unroll
        for (int j = 0; j < 4; j++)
            Out[(size_t)h * SQ * SQ + (size_t)(m0 + ty * 4 + i) * SQ + (n0 + tx * 4 + j)] = c[i][j];
}

// ---------------- K3: B_D streaming + logits + softmax ----------------
// 1 block per query row q. Thread j owns key k=j. Streams rel[q,j,:] once
// (skipped entirely for masked keys), contracts with t[h][q][:] (smem, f32x2).
__global__ void __launch_bounds__(512, 2) attn_kernel(
    const float* __restrict__ rel, const int* __restrict__ rlen,
    const int* __restrict__ lexp)
{
    __shared__ __align__(16) ulonglong2 t2s[NH * 128];  // 16 KB: t[h][D] as f32x2 pairs
    __shared__ float ls[NH * SQ];                        // 16 KB: logits [h][k]

    const int q = blockIdx.x;
    const int tid = threadIdx.x;

    // load t[*, q, *] into smem
    float* tf = (float*)t2s;
    for (int i = tid; i < NH * SQ; i += 512) {
        int h = i >> 9, Dc = i & 511;
        tf[i] = g_t[(size_t)h * SQ * SQ + (size_t)q * SQ + Dc];
    }
    __syncthreads();

    int len = rlen[0] + (lexp ? lexp[0] : 64);
    if (len > SQ) len = SQ;
    if (len < 1) len = 1;

    const int j = tid;  // key index
    float logit[NH];
    if (j < len) {
        unsigned long long acc[NH] = {0ULL,0ULL,0ULL,0ULL,0ULL,0ULL,0ULL,0ULL};
        const ulonglong2* relrow =
            (const ulonglong2*)(rel + ((size_t)q * SQ + j) * DM);
        #pragma unroll 4
        for (int i = 0; i < 128; i++) {
            ulonglong2 rv = relrow[i];
            #pragma unroll
            for (int h = 0; h < NH; h++) {
                ulonglong2 tv = t2s[h * 128 + i];
                ffma2(acc[h], rv.x, tv.x);
                ffma2(acc[h], rv.y, tv.y);
            }
        }
        #pragma unroll
        for (int h = 0; h < NH; h++) {
            float2 p = *(float2*)&acc[h];
            logit[h] = p.x + p.y + g_ac[(size_t)h * SQ * SQ + (size_t)q * SQ + j];
        }
    } else {
        #pragma unroll
        for (int h = 0; h < NH; h++) logit[h] = -1e15f;
    }
    #pragma unroll
    for (int h = 0; h < NH; h++) ls[h * SQ + j] = logit[h];
    __syncthreads();

    // softmax: warp w handles head w (16 entries per lane)
    const int w = tid >> 5, lane = tid & 31;
    if (w < NH) {
        float vb[16];
        float m = -3.4e38f;
        #pragma unroll
        for (int r = 0; r < 16; r++) {
            vb[r] = ls[w * SQ + r * 32 + lane];
            m = fmaxf(m, vb[r]);
        }
        #pragma unroll
        for (int o = 16; o; o >>= 1) m = fmaxf(m, __shfl_xor_sync(0xffffffffu, m, o));
        float sum = 0.f;
        #pragma unroll
        for (int r = 0; r < 16; r++) { vb[r] = __expf(vb[r] - m); sum += vb[r]; }
        #pragma unroll
        for (int o = 16; o; o >>= 1) sum += __shfl_xor_sync(0xffffffffu, sum, o);
        float inv = 1.0f / sum;
        #pragma unroll
        for (int r = 0; r < 16; r++)
            g_at[(size_t)w * SQ * SQ + (size_t)q * SQ + r * 32 + lane] = vb[r] * inv;
    }
}

// ---------------- K4: out[h][q][d] = sum_k attn[h][q][k] * v[h][k][d] ----------------
__global__ void __launch_bounds__(512) av_kernel()
{
    __shared__ float sa[8][SQ];                 // 16 KB attn rows
    __shared__ __align__(16) float sv[32][64];  // 8 KB  val tile

    const int h = blockIdx.y;
    const int q0 = blockIdx.x * 8;
    const int tid = threadIdx.x;

    for (int i = tid; i < 8 * SQ; i += 512) {
        int qi = i >> 9, k = i & 511;
        sa[qi][k] = g_at[(size_t)h * SQ * SQ + (size_t)(q0 + qi) * SQ + k];
    }

    const int qi = tid >> 6, d = tid & 63;
    float acc = 0.f;
    const int kk_row = tid >> 4, d4 = (tid & 15) * 4;

    for (int kc = 0; kc < SQ; kc += 32) {
        __syncthreads();
        *(float4*)&sv[kk_row][d4] =
            *(const float4*)&g_vh[(size_t)h * SQ * DH + (size_t)(kc + kk_row) * DH + d4];
        __syncthreads();
        #pragma unroll
        for (int kk = 0; kk < 32; kk++)
            acc += sa[qi][kc + kk] * sv[kk][d];
    }
    g_o[(size_t)h * SQ * DH + (size_t)(q0 + qi) * DH + d] = acc;
}

// ---------------- K5: residual + LayerNorm ----------------
__global__ void __launch_bounds__(512) ln_kernel(const float* __restrict__ query,
                                                 float* __restrict__ out)
{
    __shared__ float red[32];
    const int s = blockIdx.x, j = threadIdx.x;
    float x = query[(size_t)s * DM + j] +
              g_o[(size_t)(j >> 6) * SQ * DH + (size_t)s * DH + (j & 63)];
    float v1 = x, v2 = x * x;
    #pragma unroll
    for (int o = 16; o; o >>= 1) {
        v1 += __shfl_xor_sync(0xffffffffu, v1, o);
        v2 += __shfl_xor_sync(0xffffffffu, v2, o);
    }
    const int w = j >> 5;
    if ((j & 31) == 0) { red[w] = v1; red[w + 16] = v2; }
    __syncthreads();
    if (j < 32) {
        float a = (j < 16) ? red[j] : 0.f;
        float b = (j < 16) ? red[j + 16] : 0.f;
        #pragma unroll
        for (int o = 8; o; o >>= 1) {
            a += __shfl_xor_sync(0xffffffffu, a, o);
            b += __shfl_xor_sync(0xffffffffu, b, o);
        }
        if (j == 0) { red[0] = a; red[1] = b; }
    }
    __syncthreads();
    float mean = red[0] * (1.f / 512.f);
    float var  = red[1] * (1.f / 512.f) - mean * mean;
    out[(size_t)s * DM + j] = (x - mean) * rsqrtf(var + 1e-5f);
}

// ---------------- launch ----------------
extern "C" void kernel_launch(void* const* d_in, const int* in_sizes, int n_in,
                              void* d_out, int out_size)
{
    const float* query = (const float*)d_in[0];
    const float* key   = (const float*)d_in[1];
    const float* value = (const float*)d_in[2];
    const float* rel   = (const float*)d_in[3];
    const int*   rlen  = (const int*)d_in[4];

    int base = 5;
    const int* lexp = nullptr;
    if (n_in >= 16 && in_sizes[5] == 1) { lexp = (const int*)d_in[5]; base = 6; }

    const float* Wq = (const float*)d_in[base + 0];
    const float* bq = (const float*)d_in[base + 1];
    const float* Wk = (const float*)d_in[base + 2];
    const float* bk = (const float*)d_in[base + 3];
    const float* Wv = (const float*)d_in[base + 4];
    const float* bv = (const float*)d_in[base + 5];
    const float* Wr = (const float*)d_in[base + 6];
    // br at base+7: constant per (h,q) row -> drops out of softmax (and is zero)
    const float* u  = (const float*)d_in[base + 8];
    const float* v  = (const float*)d_in[base + 9];
    (void)out_size;

    proj_kernel<<<dim3(8, 8, 3), 256>>>(query, key, value, Wq, bq, Wk, bk, Wv, bv, u, v);
    nt64_kernel<<<dim3(8, 8, 16), 256>>>(Wr);
    attn_kernel<<<SQ, 512>>>(rel, rlen, lexp);
    av_kernel<<<dim3(64, 8), 512>>>();
    ln_kernel<<<SQ, 512>>>(query, (float*)d_out);
}